// round 14
// baseline (speedup 1.0000x reference)
#include <cuda_runtime.h>
#include <cuda_fp16.h>
#include <math.h>
#include <stdint.h>

// Problem constants
#define NB 2
#define NS 2048
#define NTOK (NB * NS)          // 4096
#define DD 1024
#define FF 2048
#define NE 16

// GEMM tiling
#define BM 256
#define BN 64
#define BK 64
#define NTHREADS_G 256          // 8 warps (4 M x 2 N), 64x32 warp tiles
#define GRID_X 32               // = NTOK/BM + NE (exact tile-count bound)

// SMEM stage layout (padded, bank-conflict-free for ldmatrix)
#define A_STRIDE 144            // 64 fp16 = 128B data + 16B pad
#define B_STRIDE 144            // 64 fp16 = 128B data + 16B pad
#define OA_H 0
#define OB_H (OA_H + BM * A_STRIDE)            // 36864
#define STAGE_BYTES (OB_H + BK * B_STRIDE)     // 46080
#define SMEM_GEMM (2 * STAGE_BYTES)            // 92160

// Router
#define RT_WARPS 16
#define RT_STRIDE 20
#define SMEM_RT (DD * RT_STRIDE * 4)   // 81920

// ---------------- device scratch (static globals: allocation-free) ----------
__device__ __half g_xh[NTOK * DD];      // gathered tokens fp16 (8 MB)
__device__ __half g_hh[NTOK * FF];      // hidden fp16 (16 MB)
__device__ int   g_assign[NTOK];
__device__ float g_wgt[NTOK];
__device__ int   g_perm[NTOK];
__device__ int   g_counts[NE];
__device__ int   g_cursor[NE];
__device__ int   g_row_start[NE];
__device__ int   g_tile_e[GRID_X];
__device__ int   g_tile_row[GRID_X];
__device__ int   g_tile_rows[GRID_X];
__device__ int   g_num_tiles;

// ---------------- helpers ----------------------------------------------------
__device__ __forceinline__ uint32_t smem_u32(const void* p) {
    uint32_t a;
    asm("{ .reg .u64 t; cvta.to.shared.u64 t, %1; cvt.u32.u64 %0, t; }" : "=r"(a) : "l"(p));
    return a;
}
__device__ __forceinline__ void cp16(uint32_t dst, const void* src, uint32_t sz) {
    asm volatile("cp.async.cg.shared.global [%0], [%1], 16, %2;"
                 :: "r"(dst), "l"(src), "r"(sz) : "memory");
}
__device__ __forceinline__ void cp_commit() {
    asm volatile("cp.async.commit_group;" ::: "memory");
}
__device__ __forceinline__ void ldsm_x4(uint32_t* r, uint32_t addr) {
    asm volatile("ldmatrix.sync.aligned.m8n8.x4.shared.b16 {%0,%1,%2,%3}, [%4];"
                 : "=r"(r[0]), "=r"(r[1]), "=r"(r[2]), "=r"(r[3]) : "r"(addr));
}
__device__ __forceinline__ void ldsm_x4_t(uint32_t* r, uint32_t addr) {
    asm volatile("ldmatrix.sync.aligned.m8n8.x4.trans.shared.b16 {%0,%1,%2,%3}, [%4];"
                 : "=r"(r[0]), "=r"(r[1]), "=r"(r[2]), "=r"(r[3]) : "r"(addr));
}
__device__ __forceinline__ void mma_f16(float* d, const uint32_t* a, const uint32_t* b) {
    asm volatile("mma.sync.aligned.m16n8k16.row.col.f32.f16.f16.f32 "
                 "{%0,%1,%2,%3}, {%4,%5,%6,%7}, {%8,%9}, {%0,%1,%2,%3};"
                 : "+f"(d[0]), "+f"(d[1]), "+f"(d[2]), "+f"(d[3])
                 : "r"(a[0]), "r"(a[1]), "r"(a[2]), "r"(a[3]), "r"(b[0]), "r"(b[1]));
}
__device__ __forceinline__ uint32_t pack_h2(float a, float b) {
    __half2 t = __floats2half2_rn(a, b);
    return *reinterpret_cast<uint32_t*>(&t);
}
__device__ __forceinline__ void sts64(uint32_t addr, uint32_t x, uint32_t y) {
    asm volatile("st.shared.v2.b32 [%0], {%1, %2};" :: "r"(addr), "r"(x), "r"(y) : "memory");
}
__device__ __forceinline__ float gelu_erf(float x) {
    return 0.5f * x * (1.0f + erff(x * 0.70710678118654752440f));
}
__device__ __forceinline__ uint2 cvt4(float4 v) {
    return make_uint2(pack_h2(v.x, v.y), pack_h2(v.z, v.w));
}

// ---------------- routing ----------------------------------------------------
__global__ void zero_kernel() {
    int t = threadIdx.x;
    if (t < NE) { g_counts[t] = 0; g_cursor[t] = 0; }
}

// router: rw cached in smem (stride 20 floats -> 16B-aligned rows, bank pattern
// conflict-free for LDS.128), 16 tokens/block
__global__ __launch_bounds__(512) void router_kernel(
    const float* __restrict__ h, const float* __restrict__ rw)
{
    extern __shared__ float srw[];   // [DD][RT_STRIDE]
    int tid = threadIdx.x, lane = tid & 31, wid = tid >> 5;
    for (int i = tid; i < DD * NE; i += 512)
        srw[(i >> 4) * RT_STRIDE + (i & 15)] = rw[i];
    __syncthreads();

    int tok = blockIdx.x * RT_WARPS + wid;
    const float* x = h + (size_t)tok * DD;
    float acc[NE];
#pragma unroll
    for (int e = 0; e < NE; e++) acc[e] = 0.0f;
    for (int d = lane; d < DD; d += 32) {
        float xv = x[d];
        const float4* r4 = (const float4*)&srw[d * RT_STRIDE];
#pragma unroll
        for (int q = 0; q < 4; q++) {
            float4 rv = r4[q];
            acc[q * 4 + 0] += xv * rv.x;
            acc[q * 4 + 1] += xv * rv.y;
            acc[q * 4 + 2] += xv * rv.z;
            acc[q * 4 + 3] += xv * rv.w;
        }
    }
#pragma unroll
    for (int e = 0; e < NE; e++)
#pragma unroll
        for (int o = 16; o > 0; o >>= 1)
            acc[e] += __shfl_down_sync(0xFFFFFFFFu, acc[e], o);
    if (lane == 0) {
        int best = 0; float bv = acc[0];
#pragma unroll
        for (int e = 1; e < NE; e++)
            if (acc[e] > bv) { bv = acc[e]; best = e; }
        g_assign[tok] = best;
        g_wgt[tok]    = 1.0f / (1.0f + expf(-bv));
        atomicAdd(&g_counts[best], 1);
    }
}

__global__ void plan_kernel() {
    if (threadIdx.x != 0) return;
    int off = 0, t = 0;
    for (int e = 0; e < NE; e++) {
        g_row_start[e] = off;
        int c = g_counts[e];
        for (int r = 0; r < c; r += BM) {
            g_tile_e[t] = e; g_tile_row[t] = off + r;
            g_tile_rows[t] = min(BM, c - r); t++;
        }
        off += c;
    }
    g_num_tiles = t;
}

// merged scatter+gather: block per token; computes sorted position, writes perm
// and the fp16 token row.
__global__ __launch_bounds__(256) void scatter_gather_kernel(const float* __restrict__ h) {
    __shared__ int spos;
    int tok = blockIdx.x;
    if (threadIdx.x == 0) {
        int e = g_assign[tok];
        int p = g_row_start[e] + atomicAdd(&g_cursor[e], 1);
        g_perm[p] = tok;
        spos = p;
    }
    __syncthreads();
    int pos = spos;
    const float4* src = (const float4*)(h + (size_t)tok * DD);
    uint2* dh = (uint2*)(g_xh + (size_t)pos * DD);
    dh[threadIdx.x] = cvt4(src[threadIdx.x]);
}

// ---------------- fp16 mma.sync grouped GEMM ---------------------------------
// 8 warps (4x2), 64x32 warp tiles, BM=256 (one tile covers a typical expert ->
// weights read/converted ONCE). BK=64. A fp16 via cp.async; B raw FP32 via LDG,
// converted fp16 in-flight, sts_B overlapped with the MMA phase.
// FINAL=false: epilogue GELU(acc+b1) -> hidden fp16
// FINAL=true : epilogue (acc+b2)*wgt -> out[perm] (fp32)

template<int K, int NN>
__device__ __forceinline__ void issue_stage_A(
    uint32_t sbase, int i, int tid, int row0, int rows, const char* gA)
{
    uint32_t st = sbase + (i & 1) * STAGE_BYTES;
    int kc = i * BK;
    // A: 256 rows x 8 16B-chunks = 2048 chunks, 8 per thread
#pragma unroll
    for (int s = 0; s < 8; s++) {
        int j = tid + s * NTHREADS_G;
        int m = j >> 3, c = j & 7;
        int mc = m < rows ? m : 0;
        const char* g = gA + ((size_t)(row0 + mc) * K + kc) * 2 + c * 16;
        uint32_t d = st + OA_H + m * A_STRIDE + c * 16;
        cp16(d, g, m < rows ? 16u : 0u);
    }
    cp_commit();
}

// load B fp32 tile (BK x BN = 64x64) for stage i: 4 float4 per thread
template<int NN>
__device__ __forceinline__ void ldg_B(
    const float* gB, int i, int tid, int n0, float4* breg)
{
    int kc = i * BK;
#pragma unroll
    for (int s = 0; s < 4; s++) {
        int j = tid + s * NTHREADS_G;   // 0..1023
        int kr = j >> 4, c = j & 15;    // row 0..63, float4-col 0..15
        breg[s] = __ldg((const float4*)(gB + (size_t)(kc + kr) * NN + n0 + c * 4));
    }
}

// convert + store B fp16 plane for stage i
__device__ __forceinline__ void sts_B(
    uint32_t sbase, int i, int tid, const float4* breg)
{
    uint32_t st = sbase + (i & 1) * STAGE_BYTES;
#pragma unroll
    for (int s = 0; s < 4; s++) {
        int j = tid + s * NTHREADS_G;
        int kr = j >> 4, c = j & 15;
        uint2 hv = cvt4(breg[s]);
        sts64(st + OB_H + kr * B_STRIDE + c * 8, hv.x, hv.y);
    }
}

template<int K, int NN, bool FINAL>
__global__ __launch_bounds__(NTHREADS_G, 2) void gemm_mma_kernel(
    const __half* __restrict__ Ain,
    const float* __restrict__ Wsrc,
    const float* __restrict__ bsrc, float* __restrict__ out)
{
    extern __shared__ char smem[];
    int t = blockIdx.x;
    if (t >= g_num_tiles) return;
    int e    = g_tile_e[t];
    int row0 = g_tile_row[t];
    int rows = g_tile_rows[t];
    int n0   = blockIdx.y * BN;

    const char* gA = (const char*)Ain;
    const float* gB = Wsrc + (size_t)e * K * NN;
    const float* bpn = bsrc + (size_t)e * NN + n0;

    uint32_t sbase = smem_u32(smem);
    int tid = threadIdx.x, lane = tid & 31, wid = tid >> 5;
    int warp_m = wid & 3;      // 4 warps in M -> 64 rows each
    int warp_n = wid >> 2;     // 2 warps in N -> 32 cols each

    const int niter = K / BK;

    float acc[4][4][4];
#pragma unroll
    for (int mt = 0; mt < 4; mt++)
#pragma unroll
        for (int nt = 0; nt < 4; nt++)
#pragma unroll
            for (int q = 0; q < 4; q++) acc[mt][nt][q] = 0.0f;

    int lr16 = lane & 15, lc8 = lane >> 4;

    float4 breg[4];
    // prologue: stage 0
    issue_stage_A<K, NN>(sbase, 0, tid, row0, rows, gA);
    ldg_B<NN>(gB, 0, tid, n0, breg);
    asm volatile("cp.async.wait_group 0;" ::: "memory");
    sts_B(sbase, 0, tid, breg);
    __syncthreads();

    for (int i = 0; i < niter; i++) {
        bool more = (i + 1 < niter);
        if (more) {
            issue_stage_A<K, NN>(sbase, i + 1, tid, row0, rows, gA);
            ldg_B<NN>(gB, i + 1, tid, n0, breg);
        }

        uint32_t st = sbase + (i & 1) * STAGE_BYTES;
#pragma unroll
        for (int ks = 0; ks < 4; ks++) {
            // overlap next-stage B convert+store with the MMA phase
            if (ks == 2 && more) sts_B(sbase, i + 1, tid, breg);

            uint32_t ah[4][4], bh[2][4];
#pragma unroll
            for (int mt = 0; mt < 4; mt++) {
                uint32_t arow = warp_m * 64 + mt * 16 + lr16;
                ldsm_x4(ah[mt], st + OA_H + arow * A_STRIDE + ks * 32 + lc8 * 16);
            }
#pragma unroll
            for (int np = 0; np < 2; np++) {
                uint32_t brow = ks * 16 + lr16;
                uint32_t bcol = warp_n * 32 + np * 16 + lc8 * 8;
                ldsm_x4_t(bh[np], st + OB_H + brow * B_STRIDE + bcol * 2);
            }
#pragma unroll
            for (int mt = 0; mt < 4; mt++)
#pragma unroll
                for (int nt = 0; nt < 4; nt++)
                    mma_f16(acc[mt][nt], ah[mt], &bh[nt >> 1][(nt & 1) * 2]);
        }

        if (more) {
            asm volatile("cp.async.wait_group 0;" ::: "memory");
            __syncthreads();
        }
    }

    // ---- epilogue ----
    int lr = lane >> 2, lc = (lane & 3) * 2;
    int   tokr[4][2];
    float wr[4][2];
#pragma unroll
    for (int mt = 0; mt < 4; mt++)
#pragma unroll
        for (int hh = 0; hh < 2; hh++) {
            int ml = warp_m * 64 + mt * 16 + lr + hh * 8;
            if (FINAL && ml < rows) {
                int tok = g_perm[row0 + ml];
                tokr[mt][hh] = tok;
                wr[mt][hh]   = g_wgt[tok];
            } else {
                tokr[mt][hh] = 0; wr[mt][hh] = 0.f;
            }
        }

#pragma unroll
    for (int nt = 0; nt < 4; nt++) {
        int ncl = warp_n * 32 + nt * 8 + lc;
        float b0 = __ldg(bpn + ncl), b1 = __ldg(bpn + ncl + 1);
#pragma unroll
        for (int mt = 0; mt < 4; mt++)
#pragma unroll
            for (int hh = 0; hh < 2; hh++) {
                int ml = warp_m * 64 + mt * 16 + lr + hh * 8;
                if (ml >= rows) continue;
                float v0 = acc[mt][nt][2 * hh]     + b0;
                float v1 = acc[mt][nt][2 * hh + 1] + b1;
                if (FINAL) {
                    float w = wr[mt][hh];
                    float2* o = (float2*)(out + (size_t)tokr[mt][hh] * NN + n0 + ncl);
                    *o = make_float2(v0 * w, v1 * w);
                } else {
                    float g0 = gelu_erf(v0), g1 = gelu_erf(v1);
                    size_t idx = (size_t)(row0 + ml) * NN + n0 + ncl;
                    *(uint32_t*)(g_hh + idx) = pack_h2(g0, g1);
                }
            }
    }
}

// ---------------- launch -----------------------------------------------------
extern "C" void kernel_launch(void* const* d_in, const int* in_sizes, int n_in,
                              void* d_out, int out_size)
{
    const float* h  = (const float*)d_in[0];   // (B,S,D)
    const float* rw = (const float*)d_in[1];   // (D,E)
    const float* w1 = (const float*)d_in[2];   // (E,D,F)
    const float* b1 = (const float*)d_in[3];   // (E,F)
    const float* w2 = (const float*)d_in[4];   // (E,F,D)
    const float* b2 = (const float*)d_in[5];   // (E,D)
    float* out = (float*)d_out;                // (B,S,D)

    cudaFuncSetAttribute(gemm_mma_kernel<DD, FF, false>,
                         cudaFuncAttributeMaxDynamicSharedMemorySize, SMEM_GEMM);
    cudaFuncSetAttribute(gemm_mma_kernel<FF, DD, true>,
                         cudaFuncAttributeMaxDynamicSharedMemorySize, SMEM_GEMM);
    cudaFuncSetAttribute(router_kernel,
                         cudaFuncAttributeMaxDynamicSharedMemorySize, SMEM_RT);

    __half *xh, *hh;
    cudaGetSymbolAddress((void**)&xh, g_xh);
    cudaGetSymbolAddress((void**)&hh, g_hh);

    zero_kernel<<<1, 32>>>();
    router_kernel<<<NTOK / RT_WARPS, 512, SMEM_RT>>>(h, rw);
    plan_kernel<<<1, 32>>>();
    scatter_gather_kernel<<<NTOK, 256>>>(h);

    gemm_mma_kernel<DD, FF, false><<<dim3(GRID_X, FF / BN), NTHREADS_G, SMEM_GEMM>>>(
        xh, w1, b1, nullptr);
    gemm_mma_kernel<FF, DD, true><<<dim3(GRID_X, DD / BN), NTHREADS_G, SMEM_GEMM>>>(
        hh, w2, b2, out);
}

// round 15
// speedup vs baseline: 1.1402x; 1.1402x over previous
#include <cuda_runtime.h>
#include <cuda_fp16.h>
#include <math.h>
#include <stdint.h>

// Problem constants
#define NB 2
#define NS 2048
#define NTOK (NB * NS)          // 4096
#define DD 1024
#define FF 2048
#define NE 16

// GEMM tiling
#define BM 128
#define BN 64
#define BK 64
#define NTHREADS_G 128          // 4 warps (2 M x 2 N), 64x32 warp tiles
#define GRID_X 48               // = NTOK/BM + NE (exact tile-count bound)

// SMEM stage layout (padded, bank-conflict-free for ldmatrix)
#define A_STRIDE 144            // 64 fp16 = 128B data + 16B pad
#define B_STRIDE 144            // 64 fp16 = 128B data + 16B pad
#define OA_H 0
#define OB_H (OA_H + BM * A_STRIDE)            // 18432
#define STAGE_BYTES (OB_H + BK * B_STRIDE)     // 27648
#define SMEM_GEMM (2 * STAGE_BYTES)            // 55296

// Router
#define RT_WARPS 16
#define RT_STRIDE 20
#define SMEM_RT (DD * RT_STRIDE * 4)   // 81920

// ---------------- device scratch (static globals: allocation-free) ----------
__device__ __half g_xh[NTOK * DD];      // gathered tokens fp16 (8 MB)
__device__ __half g_hh[NTOK * FF];      // hidden fp16 (16 MB)
__device__ int   g_assign[NTOK];
__device__ float g_wgt[NTOK];
__device__ int   g_perm[NTOK];
__device__ int   g_counts[NE];
__device__ int   g_cursor[NE];
__device__ int   g_row_start[NE];
__device__ int   g_tile_e[GRID_X];
__device__ int   g_tile_row[GRID_X];
__device__ int   g_tile_rows[GRID_X];
__device__ int   g_num_tiles;

// ---------------- helpers ----------------------------------------------------
__device__ __forceinline__ uint32_t smem_u32(const void* p) {
    uint32_t a;
    asm("{ .reg .u64 t; cvta.to.shared.u64 t, %1; cvt.u32.u64 %0, t; }" : "=r"(a) : "l"(p));
    return a;
}
__device__ __forceinline__ void cp16(uint32_t dst, const void* src, uint32_t sz) {
    asm volatile("cp.async.cg.shared.global [%0], [%1], 16, %2;"
                 :: "r"(dst), "l"(src), "r"(sz) : "memory");
}
__device__ __forceinline__ void cp_commit() {
    asm volatile("cp.async.commit_group;" ::: "memory");
}
__device__ __forceinline__ void ldsm_x4(uint32_t* r, uint32_t addr) {
    asm volatile("ldmatrix.sync.aligned.m8n8.x4.shared.b16 {%0,%1,%2,%3}, [%4];"
                 : "=r"(r[0]), "=r"(r[1]), "=r"(r[2]), "=r"(r[3]) : "r"(addr));
}
__device__ __forceinline__ void ldsm_x4_t(uint32_t* r, uint32_t addr) {
    asm volatile("ldmatrix.sync.aligned.m8n8.x4.trans.shared.b16 {%0,%1,%2,%3}, [%4];"
                 : "=r"(r[0]), "=r"(r[1]), "=r"(r[2]), "=r"(r[3]) : "r"(addr));
}
__device__ __forceinline__ void mma_f16(float* d, const uint32_t* a, const uint32_t* b) {
    asm volatile("mma.sync.aligned.m16n8k16.row.col.f32.f16.f16.f32 "
                 "{%0,%1,%2,%3}, {%4,%5,%6,%7}, {%8,%9}, {%0,%1,%2,%3};"
                 : "+f"(d[0]), "+f"(d[1]), "+f"(d[2]), "+f"(d[3])
                 : "r"(a[0]), "r"(a[1]), "r"(a[2]), "r"(a[3]), "r"(b[0]), "r"(b[1]));
}
__device__ __forceinline__ uint32_t pack_h2(float a, float b) {
    __half2 t = __floats2half2_rn(a, b);
    return *reinterpret_cast<uint32_t*>(&t);
}
__device__ __forceinline__ void sts64(uint32_t addr, uint32_t x, uint32_t y) {
    asm volatile("st.shared.v2.b32 [%0], {%1, %2};" :: "r"(addr), "r"(x), "r"(y) : "memory");
}
__device__ __forceinline__ float gelu_erf(float x) {
    return 0.5f * x * (1.0f + erff(x * 0.70710678118654752440f));
}
__device__ __forceinline__ uint2 cvt4(float4 v) {
    return make_uint2(pack_h2(v.x, v.y), pack_h2(v.z, v.w));
}

// ---------------- routing ----------------------------------------------------
__global__ void zero_kernel() {
    int t = threadIdx.x;
    if (t < NE) { g_counts[t] = 0; g_cursor[t] = 0; }
}

// router: rw cached in smem (stride 20 floats -> 16B-aligned rows, bank pattern
// conflict-free for LDS.128), 16 tokens/block
__global__ __launch_bounds__(512) void router_kernel(
    const float* __restrict__ h, const float* __restrict__ rw)
{
    extern __shared__ float srw[];   // [DD][RT_STRIDE]
    int tid = threadIdx.x, lane = tid & 31, wid = tid >> 5;
    for (int i = tid; i < DD * NE; i += 512)
        srw[(i >> 4) * RT_STRIDE + (i & 15)] = rw[i];
    __syncthreads();

    int tok = blockIdx.x * RT_WARPS + wid;
    const float* x = h + (size_t)tok * DD;
    float acc[NE];
#pragma unroll
    for (int e = 0; e < NE; e++) acc[e] = 0.0f;
    for (int d = lane; d < DD; d += 32) {
        float xv = x[d];
        const float4* r4 = (const float4*)&srw[d * RT_STRIDE];
#pragma unroll
        for (int q = 0; q < 4; q++) {
            float4 rv = r4[q];
            acc[q * 4 + 0] += xv * rv.x;
            acc[q * 4 + 1] += xv * rv.y;
            acc[q * 4 + 2] += xv * rv.z;
            acc[q * 4 + 3] += xv * rv.w;
        }
    }
#pragma unroll
    for (int e = 0; e < NE; e++)
#pragma unroll
        for (int o = 16; o > 0; o >>= 1)
            acc[e] += __shfl_down_sync(0xFFFFFFFFu, acc[e], o);
    if (lane == 0) {
        int best = 0; float bv = acc[0];
#pragma unroll
        for (int e = 1; e < NE; e++)
            if (acc[e] > bv) { bv = acc[e]; best = e; }
        g_assign[tok] = best;
        g_wgt[tok]    = 1.0f / (1.0f + expf(-bv));
        atomicAdd(&g_counts[best], 1);
    }
}

__global__ void plan_kernel() {
    if (threadIdx.x != 0) return;
    int off = 0, t = 0;
    for (int e = 0; e < NE; e++) {
        g_row_start[e] = off;
        int c = g_counts[e];
        for (int r = 0; r < c; r += BM) {
            g_tile_e[t] = e; g_tile_row[t] = off + r;
            g_tile_rows[t] = min(BM, c - r); t++;
        }
        off += c;
    }
    g_num_tiles = t;
}

// merged scatter+gather: block per token; computes sorted position, writes perm
// and the fp16 token row.
__global__ __launch_bounds__(256) void scatter_gather_kernel(const float* __restrict__ h) {
    __shared__ int spos;
    int tok = blockIdx.x;
    if (threadIdx.x == 0) {
        int e = g_assign[tok];
        int p = g_row_start[e] + atomicAdd(&g_cursor[e], 1);
        g_perm[p] = tok;
        spos = p;
    }
    __syncthreads();
    int pos = spos;
    const float4* src = (const float4*)(h + (size_t)tok * DD);
    uint2* dh = (uint2*)(g_xh + (size_t)pos * DD);
    dh[threadIdx.x] = cvt4(src[threadIdx.x]);
}

// ---------------- fp16 mma.sync grouped GEMM ---------------------------------
// 4 warps (2x2), 64x32 warp tiles, BK=64. A fp16 via cp.async; B raw FP32 via
// LDG, converted fp16 in-flight, sts_B overlapped with the MMA phase.
// Fragments are double-buffered in registers: ks+1 ldsm issues before ks MMAs,
// hiding ldsm latency behind MMA issue.
// FINAL=false: epilogue GELU(acc+b1) -> hidden fp16
// FINAL=true : epilogue (acc+b2)*wgt -> out[perm] (fp32)

template<int K, int NN>
__device__ __forceinline__ void issue_stage_A(
    uint32_t sbase, int i, int tid, int row0, int rows, const char* gA)
{
    uint32_t st = sbase + (i & 1) * STAGE_BYTES;
    int kc = i * BK;
    // A: 128 rows x 8 16B-chunks = 1024 chunks, 8 per thread
#pragma unroll
    for (int s = 0; s < 8; s++) {
        int j = tid + s * NTHREADS_G;
        int m = j >> 3, c = j & 7;
        int mc = m < rows ? m : 0;
        const char* g = gA + ((size_t)(row0 + mc) * K + kc) * 2 + c * 16;
        uint32_t d = st + OA_H + m * A_STRIDE + c * 16;
        cp16(d, g, m < rows ? 16u : 0u);
    }
    cp_commit();
}

// load B fp32 tile (BK x BN = 64x64) for stage i: 8 float4 per thread
template<int NN>
__device__ __forceinline__ void ldg_B(
    const float* gB, int i, int tid, int n0, float4* breg)
{
    int kc = i * BK;
#pragma unroll
    for (int s = 0; s < 8; s++) {
        int j = tid + s * NTHREADS_G;   // 0..1023
        int kr = j >> 4, c = j & 15;    // row 0..63, float4-col 0..15
        breg[s] = __ldg((const float4*)(gB + (size_t)(kc + kr) * NN + n0 + c * 4));
    }
}

// convert + store B fp16 plane for stage i
__device__ __forceinline__ void sts_B(
    uint32_t sbase, int i, int tid, const float4* breg)
{
    uint32_t st = sbase + (i & 1) * STAGE_BYTES;
#pragma unroll
    for (int s = 0; s < 8; s++) {
        int j = tid + s * NTHREADS_G;
        int kr = j >> 4, c = j & 15;
        uint2 hv = cvt4(breg[s]);
        sts64(st + OB_H + kr * B_STRIDE + c * 8, hv.x, hv.y);
    }
}

// load all fragments for one ks step
__device__ __forceinline__ void load_frag(
    uint32_t st, int ks, int warp_m, int warp_n, int lr16, int lc8,
    uint32_t ah[4][4], uint32_t bh[2][4])
{
#pragma unroll
    for (int mt = 0; mt < 4; mt++) {
        uint32_t arow = warp_m * 64 + mt * 16 + lr16;
        ldsm_x4(ah[mt], st + OA_H + arow * A_STRIDE + ks * 32 + lc8 * 16);
    }
#pragma unroll
    for (int np = 0; np < 2; np++) {
        uint32_t brow = ks * 16 + lr16;
        uint32_t bcol = warp_n * 32 + np * 16 + lc8 * 8;
        ldsm_x4_t(bh[np], st + OB_H + brow * B_STRIDE + bcol * 2);
    }
}

template<int K, int NN, bool FINAL>
__global__ __launch_bounds__(NTHREADS_G, 3) void gemm_mma_kernel(
    const __half* __restrict__ Ain,
    const float* __restrict__ Wsrc,
    const float* __restrict__ bsrc, float* __restrict__ out)
{
    extern __shared__ char smem[];
    int t = blockIdx.x;
    if (t >= g_num_tiles) return;
    int e    = g_tile_e[t];
    int row0 = g_tile_row[t];
    int rows = g_tile_rows[t];
    int n0   = blockIdx.y * BN;

    const char* gA = (const char*)Ain;
    const float* gB = Wsrc + (size_t)e * K * NN;
    const float* bpn = bsrc + (size_t)e * NN + n0;

    uint32_t sbase = smem_u32(smem);
    int tid = threadIdx.x, lane = tid & 31, wid = tid >> 5;
    int warp_m = wid & 1;      // 2 warps in M -> 64 rows each
    int warp_n = wid >> 1;     // 2 warps in N -> 32 cols each

    const int niter = K / BK;

    float acc[4][4][4];
#pragma unroll
    for (int mt = 0; mt < 4; mt++)
#pragma unroll
        for (int nt = 0; nt < 4; nt++)
#pragma unroll
            for (int q = 0; q < 4; q++) acc[mt][nt][q] = 0.0f;

    int lr16 = lane & 15, lc8 = lane >> 4;

    float4 breg[8];
    // prologue: stage 0
    issue_stage_A<K, NN>(sbase, 0, tid, row0, rows, gA);
    ldg_B<NN>(gB, 0, tid, n0, breg);
    asm volatile("cp.async.wait_group 0;" ::: "memory");
    sts_B(sbase, 0, tid, breg);
    __syncthreads();

    for (int i = 0; i < niter; i++) {
        bool more = (i + 1 < niter);
        if (more) {
            issue_stage_A<K, NN>(sbase, i + 1, tid, row0, rows, gA);
            ldg_B<NN>(gB, i + 1, tid, n0, breg);
        }

        uint32_t st = sbase + (i & 1) * STAGE_BYTES;
        uint32_t ah[2][4][4], bh[2][2][4];
        load_frag(st, 0, warp_m, warp_n, lr16, lc8, ah[0], bh[0]);
#pragma unroll
        for (int ks = 0; ks < 4; ks++) {
            int cur = ks & 1;
            // prefetch next ks fragments before issuing this ks's MMAs
            if (ks < 3)
                load_frag(st, ks + 1, warp_m, warp_n, lr16, lc8, ah[cur ^ 1], bh[cur ^ 1]);
            // overlap next-stage B convert+store with the MMA phase
            if (ks == 2 && more) sts_B(sbase, i + 1, tid, breg);
#pragma unroll
            for (int mt = 0; mt < 4; mt++)
#pragma unroll
                for (int nt = 0; nt < 4; nt++)
                    mma_f16(acc[mt][nt], ah[cur][mt], &bh[cur][nt >> 1][(nt & 1) * 2]);
        }

        if (more) {
            asm volatile("cp.async.wait_group 0;" ::: "memory");
            __syncthreads();
        }
    }

    // ---- epilogue ----
    int lr = lane >> 2, lc = (lane & 3) * 2;
    int   tokr[4][2];
    float wr[4][2];
#pragma unroll
    for (int mt = 0; mt < 4; mt++)
#pragma unroll
        for (int hh = 0; hh < 2; hh++) {
            int ml = warp_m * 64 + mt * 16 + lr + hh * 8;
            if (FINAL && ml < rows) {
                int tok = g_perm[row0 + ml];
                tokr[mt][hh] = tok;
                wr[mt][hh]   = g_wgt[tok];
            } else {
                tokr[mt][hh] = 0; wr[mt][hh] = 0.f;
            }
        }

#pragma unroll
    for (int nt = 0; nt < 4; nt++) {
        int ncl = warp_n * 32 + nt * 8 + lc;
        float b0 = __ldg(bpn + ncl), b1 = __ldg(bpn + ncl + 1);
#pragma unroll
        for (int mt = 0; mt < 4; mt++)
#pragma unroll
            for (int hh = 0; hh < 2; hh++) {
                int ml = warp_m * 64 + mt * 16 + lr + hh * 8;
                if (ml >= rows) continue;
                float v0 = acc[mt][nt][2 * hh]     + b0;
                float v1 = acc[mt][nt][2 * hh + 1] + b1;
                if (FINAL) {
                    float w = wr[mt][hh];
                    float2* o = (float2*)(out + (size_t)tokr[mt][hh] * NN + n0 + ncl);
                    *o = make_float2(v0 * w, v1 * w);
                } else {
                    float g0 = gelu_erf(v0), g1 = gelu_erf(v1);
                    size_t idx = (size_t)(row0 + ml) * NN + n0 + ncl;
                    *(uint32_t*)(g_hh + idx) = pack_h2(g0, g1);
                }
            }
    }
}

// ---------------- launch -----------------------------------------------------
extern "C" void kernel_launch(void* const* d_in, const int* in_sizes, int n_in,
                              void* d_out, int out_size)
{
    const float* h  = (const float*)d_in[0];   // (B,S,D)
    const float* rw = (const float*)d_in[1];   // (D,E)
    const float* w1 = (const float*)d_in[2];   // (E,D,F)
    const float* b1 = (const float*)d_in[3];   // (E,F)
    const float* w2 = (const float*)d_in[4];   // (E,F,D)
    const float* b2 = (const float*)d_in[5];   // (E,D)
    float* out = (float*)d_out;                // (B,S,D)

    cudaFuncSetAttribute(gemm_mma_kernel<DD, FF, false>,
                         cudaFuncAttributeMaxDynamicSharedMemorySize, SMEM_GEMM);
    cudaFuncSetAttribute(gemm_mma_kernel<FF, DD, true>,
                         cudaFuncAttributeMaxDynamicSharedMemorySize, SMEM_GEMM);
    cudaFuncSetAttribute(router_kernel,
                         cudaFuncAttributeMaxDynamicSharedMemorySize, SMEM_RT);

    __half *xh, *hh;
    cudaGetSymbolAddress((void**)&xh, g_xh);
    cudaGetSymbolAddress((void**)&hh, g_hh);

    zero_kernel<<<1, 32>>>();
    router_kernel<<<NTOK / RT_WARPS, 512, SMEM_RT>>>(h, rw);
    plan_kernel<<<1, 32>>>();
    scatter_gather_kernel<<<NTOK, 256>>>(h);

    gemm_mma_kernel<DD, FF, false><<<dim3(GRID_X, FF / BN), NTHREADS_G, SMEM_GEMM>>>(
        xh, w1, b1, nullptr);
    gemm_mma_kernel<FF, DD, true><<<dim3(GRID_X, DD / BN), NTHREADS_G, SMEM_GEMM>>>(
        hh, w2, b2, out);
}

// round 16
// speedup vs baseline: 1.1955x; 1.0485x over previous
#include <cuda_runtime.h>
#include <cuda_fp16.h>
#include <math.h>
#include <stdint.h>

// Problem constants
#define NB 2
#define NS 2048
#define NTOK (NB * NS)          // 4096
#define DD 1024
#define FF 2048
#define NE 16

// GEMM tiling
#define BM 128
#define BN 64
#define BK 64
#define NTHREADS_G 128          // 4 warps (2 M x 2 N), 64x32 warp tiles
#define GRID_X 48               // = NTOK/BM + NE (exact tile-count bound)

// SMEM stage layout (padded, bank-conflict-free for ldmatrix)
#define A_STRIDE 144            // 64 fp16 = 128B data + 16B pad
#define B_STRIDE 144            // 64 fp16 = 128B data + 16B pad
#define OA_H 0
#define OB_H (OA_H + BM * A_STRIDE)            // 18432
#define STAGE_BYTES (OB_H + BK * B_STRIDE)     // 27648
#define SMEM_GEMM (2 * STAGE_BYTES)            // 55296

// Router
#define RT_WARPS 16
#define RT_STRIDE 20
#define SMEM_RT (DD * RT_STRIDE * 4)   // 81920

// ---------------- device scratch (static globals: allocation-free) ----------
// NOTE: statically zero-initialized; counts re-zeroed by plan_kernel, cursor
// re-zeroed by gemm1 tile-0 block -> every call starts from zeroed state.
__device__ __half g_xh[NTOK * DD];      // gathered tokens fp16 (8 MB)
__device__ __half g_hh[NTOK * FF];      // hidden fp16 (16 MB)
__device__ int   g_assign[NTOK];
__device__ float g_wgt[NTOK];
__device__ int   g_perm[NTOK];
__device__ int   g_counts[NE];
__device__ int   g_cursor[NE];
__device__ int   g_row_start[NE];
__device__ int   g_tile_e[GRID_X];
__device__ int   g_tile_row[GRID_X];
__device__ int   g_tile_rows[GRID_X];
__device__ int   g_num_tiles;

// ---------------- helpers ----------------------------------------------------
__device__ __forceinline__ uint32_t smem_u32(const void* p) {
    uint32_t a;
    asm("{ .reg .u64 t; cvta.to.shared.u64 t, %1; cvt.u32.u64 %0, t; }" : "=r"(a) : "l"(p));
    return a;
}
__device__ __forceinline__ void cp16(uint32_t dst, const void* src, uint32_t sz) {
    asm volatile("cp.async.cg.shared.global [%0], [%1], 16, %2;"
                 :: "r"(dst), "l"(src), "r"(sz) : "memory");
}
__device__ __forceinline__ void cp_commit() {
    asm volatile("cp.async.commit_group;" ::: "memory");
}
__device__ __forceinline__ void ldsm_x4(uint32_t* r, uint32_t addr) {
    asm volatile("ldmatrix.sync.aligned.m8n8.x4.shared.b16 {%0,%1,%2,%3}, [%4];"
                 : "=r"(r[0]), "=r"(r[1]), "=r"(r[2]), "=r"(r[3]) : "r"(addr));
}
__device__ __forceinline__ void ldsm_x4_t(uint32_t* r, uint32_t addr) {
    asm volatile("ldmatrix.sync.aligned.m8n8.x4.trans.shared.b16 {%0,%1,%2,%3}, [%4];"
                 : "=r"(r[0]), "=r"(r[1]), "=r"(r[2]), "=r"(r[3]) : "r"(addr));
}
__device__ __forceinline__ void mma_f16(float* d, const uint32_t* a, const uint32_t* b) {
    asm volatile("mma.sync.aligned.m16n8k16.row.col.f32.f16.f16.f32 "
                 "{%0,%1,%2,%3}, {%4,%5,%6,%7}, {%8,%9}, {%0,%1,%2,%3};"
                 : "+f"(d[0]), "+f"(d[1]), "+f"(d[2]), "+f"(d[3])
                 : "r"(a[0]), "r"(a[1]), "r"(a[2]), "r"(a[3]), "r"(b[0]), "r"(b[1]));
}
__device__ __forceinline__ uint32_t pack_h2(float a, float b) {
    __half2 t = __floats2half2_rn(a, b);
    return *reinterpret_cast<uint32_t*>(&t);
}
__device__ __forceinline__ void sts64(uint32_t addr, uint32_t x, uint32_t y) {
    asm volatile("st.shared.v2.b32 [%0], {%1, %2};" :: "r"(addr), "r"(x), "r"(y) : "memory");
}
__device__ __forceinline__ float gelu_erf(float x) {
    return 0.5f * x * (1.0f + erff(x * 0.70710678118654752440f));
}
__device__ __forceinline__ uint2 cvt4(float4 v) {
    return make_uint2(pack_h2(v.x, v.y), pack_h2(v.z, v.w));
}

// ---------------- routing ----------------------------------------------------
// router: rw cached in smem (stride 20 floats -> 16B-aligned rows, bank pattern
// conflict-free for LDS.128), 16 tokens/block
__global__ __launch_bounds__(512) void router_kernel(
    const float* __restrict__ h, const float* __restrict__ rw)
{
    extern __shared__ float srw[];   // [DD][RT_STRIDE]
    int tid = threadIdx.x, lane = tid & 31, wid = tid >> 5;
    for (int i = tid; i < DD * NE; i += 512)
        srw[(i >> 4) * RT_STRIDE + (i & 15)] = rw[i];
    __syncthreads();

    int tok = blockIdx.x * RT_WARPS + wid;
    const float* x = h + (size_t)tok * DD;
    float acc[NE];
#pragma unroll
    for (int e = 0; e < NE; e++) acc[e] = 0.0f;
    for (int d = lane; d < DD; d += 32) {
        float xv = x[d];
        const float4* r4 = (const float4*)&srw[d * RT_STRIDE];
#pragma unroll
        for (int q = 0; q < 4; q++) {
            float4 rv = r4[q];
            acc[q * 4 + 0] += xv * rv.x;
            acc[q * 4 + 1] += xv * rv.y;
            acc[q * 4 + 2] += xv * rv.z;
            acc[q * 4 + 3] += xv * rv.w;
        }
    }
#pragma unroll
    for (int e = 0; e < NE; e++)
#pragma unroll
        for (int o = 16; o > 0; o >>= 1)
            acc[e] += __shfl_down_sync(0xFFFFFFFFu, acc[e], o);
    if (lane == 0) {
        int best = 0; float bv = acc[0];
#pragma unroll
        for (int e = 1; e < NE; e++)
            if (acc[e] > bv) { bv = acc[e]; best = e; }
        g_assign[tok] = best;
        g_wgt[tok]    = 1.0f / (1.0f + expf(-bv));
        atomicAdd(&g_counts[best], 1);
    }
}

// plan: build tile map, then re-zero counts for the next call
__global__ void plan_kernel() {
    if (threadIdx.x != 0) return;
    int off = 0, t = 0;
    for (int e = 0; e < NE; e++) {
        g_row_start[e] = off;
        int c = g_counts[e];
        g_counts[e] = 0;                 // reset for next kernel_launch call
        for (int r = 0; r < c; r += BM) {
            g_tile_e[t] = e; g_tile_row[t] = off + r;
            g_tile_rows[t] = min(BM, c - r); t++;
        }
        off += c;
    }
    g_num_tiles = t;
}

// merged scatter+gather: block per token; computes sorted position, writes perm
// and the fp16 token row.
__global__ __launch_bounds__(256) void scatter_gather_kernel(const float* __restrict__ h) {
    __shared__ int spos;
    int tok = blockIdx.x;
    if (threadIdx.x == 0) {
        int e = g_assign[tok];
        int p = g_row_start[e] + atomicAdd(&g_cursor[e], 1);
        g_perm[p] = tok;
        spos = p;
    }
    __syncthreads();
    int pos = spos;
    const float4* src = (const float4*)(h + (size_t)tok * DD);
    uint2* dh = (uint2*)(g_xh + (size_t)pos * DD);
    dh[threadIdx.x] = cvt4(src[threadIdx.x]);
}

// ---------------- fp16 mma.sync grouped GEMM ---------------------------------
// 4 warps (2x2), 64x32 warp tiles, BK=64. A fp16 via cp.async; B raw FP32 via
// LDG, converted fp16 in-flight, sts_B overlapped with the MMA phase.
// FINAL=false: epilogue GELU(acc+b1) -> hidden fp16; also re-zeroes g_cursor.
// FINAL=true : epilogue (acc+b2)*wgt -> out[perm] (fp32)

template<int K, int NN>
__device__ __forceinline__ void issue_stage_A(
    uint32_t sbase, int i, int tid, int row0, int rows, const char* gA)
{
    uint32_t st = sbase + (i & 1) * STAGE_BYTES;
    int kc = i * BK;
    // A: 128 rows x 8 16B-chunks = 1024 chunks, 8 per thread
#pragma unroll
    for (int s = 0; s < 8; s++) {
        int j = tid + s * NTHREADS_G;
        int m = j >> 3, c = j & 7;
        int mc = m < rows ? m : 0;
        const char* g = gA + ((size_t)(row0 + mc) * K + kc) * 2 + c * 16;
        uint32_t d = st + OA_H + m * A_STRIDE + c * 16;
        cp16(d, g, m < rows ? 16u : 0u);
    }
    cp_commit();
}

// load B fp32 tile (BK x BN = 64x64) for stage i: 8 float4 per thread
template<int NN>
__device__ __forceinline__ void ldg_B(
    const float* gB, int i, int tid, int n0, float4* breg)
{
    int kc = i * BK;
#pragma unroll
    for (int s = 0; s < 8; s++) {
        int j = tid + s * NTHREADS_G;   // 0..1023
        int kr = j >> 4, c = j & 15;    // row 0..63, float4-col 0..15
        breg[s] = __ldg((const float4*)(gB + (size_t)(kc + kr) * NN + n0 + c * 4));
    }
}

// convert + store B fp16 plane for stage i
__device__ __forceinline__ void sts_B(
    uint32_t sbase, int i, int tid, const float4* breg)
{
    uint32_t st = sbase + (i & 1) * STAGE_BYTES;
#pragma unroll
    for (int s = 0; s < 8; s++) {
        int j = tid + s * NTHREADS_G;
        int kr = j >> 4, c = j & 15;
        uint2 hv = cvt4(breg[s]);
        sts64(st + OB_H + kr * B_STRIDE + c * 8, hv.x, hv.y);
    }
}

template<int K, int NN, bool FINAL>
__global__ __launch_bounds__(NTHREADS_G) void gemm_mma_kernel(
    const __half* __restrict__ Ain,
    const float* __restrict__ Wsrc,
    const float* __restrict__ bsrc, float* __restrict__ out)
{
    extern __shared__ char smem[];
    int t = blockIdx.x;
    // GEMM1 tile-0/n-tile-0 block re-zeroes cursor for the next call
    // (scatter_gather has fully consumed it by the time gemm1 runs).
    if (!FINAL && t == 0 && blockIdx.y == 0 && threadIdx.x < NE)
        g_cursor[threadIdx.x] = 0;
    if (t >= g_num_tiles) return;
    int e    = g_tile_e[t];
    int row0 = g_tile_row[t];
    int rows = g_tile_rows[t];
    int n0   = blockIdx.y * BN;

    const char* gA = (const char*)Ain;
    const float* gB = Wsrc + (size_t)e * K * NN;
    const float* bpn = bsrc + (size_t)e * NN + n0;

    uint32_t sbase = smem_u32(smem);
    int tid = threadIdx.x, lane = tid & 31, wid = tid >> 5;
    int warp_m = wid & 1;      // 2 warps in M -> 64 rows each
    int warp_n = wid >> 1;     // 2 warps in N -> 32 cols each

    const int niter = K / BK;

    float acc[4][4][4];
#pragma unroll
    for (int mt = 0; mt < 4; mt++)
#pragma unroll
        for (int nt = 0; nt < 4; nt++)
#pragma unroll
            for (int q = 0; q < 4; q++) acc[mt][nt][q] = 0.0f;

    int lr16 = lane & 15, lc8 = lane >> 4;

    float4 breg[8];
    // prologue: stage 0
    issue_stage_A<K, NN>(sbase, 0, tid, row0, rows, gA);
    ldg_B<NN>(gB, 0, tid, n0, breg);
    asm volatile("cp.async.wait_group 0;" ::: "memory");
    sts_B(sbase, 0, tid, breg);
    __syncthreads();

    for (int i = 0; i < niter; i++) {
        bool more = (i + 1 < niter);
        if (more) {
            issue_stage_A<K, NN>(sbase, i + 1, tid, row0, rows, gA);
            ldg_B<NN>(gB, i + 1, tid, n0, breg);
        }

        uint32_t st = sbase + (i & 1) * STAGE_BYTES;
#pragma unroll
        for (int ks = 0; ks < 4; ks++) {
            // overlap next-stage B convert+store with the MMA phase
            if (ks == 2 && more) sts_B(sbase, i + 1, tid, breg);

            uint32_t ah[4][4], bh[2][4];
#pragma unroll
            for (int mt = 0; mt < 4; mt++) {
                uint32_t arow = warp_m * 64 + mt * 16 + lr16;
                ldsm_x4(ah[mt], st + OA_H + arow * A_STRIDE + ks * 32 + lc8 * 16);
            }
#pragma unroll
            for (int np = 0; np < 2; np++) {
                uint32_t brow = ks * 16 + lr16;
                uint32_t bcol = warp_n * 32 + np * 16 + lc8 * 8;
                ldsm_x4_t(bh[np], st + OB_H + brow * B_STRIDE + bcol * 2);
            }
#pragma unroll
            for (int mt = 0; mt < 4; mt++)
#pragma unroll
                for (int nt = 0; nt < 4; nt++)
                    mma_f16(acc[mt][nt], ah[mt], &bh[nt >> 1][(nt & 1) * 2]);
        }

        if (more) {
            asm volatile("cp.async.wait_group 0;" ::: "memory");
            __syncthreads();
        }
    }

    // ---- epilogue ----
    int lr = lane >> 2, lc = (lane & 3) * 2;
    int   tokr[4][2];
    float wr[4][2];
#pragma unroll
    for (int mt = 0; mt < 4; mt++)
#pragma unroll
        for (int hh = 0; hh < 2; hh++) {
            int ml = warp_m * 64 + mt * 16 + lr + hh * 8;
            if (FINAL && ml < rows) {
                int tok = g_perm[row0 + ml];
                tokr[mt][hh] = tok;
                wr[mt][hh]   = g_wgt[tok];
            } else {
                tokr[mt][hh] = 0; wr[mt][hh] = 0.f;
            }
        }

#pragma unroll
    for (int nt = 0; nt < 4; nt++) {
        int ncl = warp_n * 32 + nt * 8 + lc;
        float b0 = __ldg(bpn + ncl), b1 = __ldg(bpn + ncl + 1);
#pragma unroll
        for (int mt = 0; mt < 4; mt++)
#pragma unroll
            for (int hh = 0; hh < 2; hh++) {
                int ml = warp_m * 64 + mt * 16 + lr + hh * 8;
                if (ml >= rows) continue;
                float v0 = acc[mt][nt][2 * hh]     + b0;
                float v1 = acc[mt][nt][2 * hh + 1] + b1;
                if (FINAL) {
                    float w = wr[mt][hh];
                    float2* o = (float2*)(out + (size_t)tokr[mt][hh] * NN + n0 + ncl);
                    *o = make_float2(v0 * w, v1 * w);
                } else {
                    float g0 = gelu_erf(v0), g1 = gelu_erf(v1);
                    size_t idx = (size_t)(row0 + ml) * NN + n0 + ncl;
                    *(uint32_t*)(g_hh + idx) = pack_h2(g0, g1);
                }
            }
    }
}

// ---------------- launch -----------------------------------------------------
extern "C" void kernel_launch(void* const* d_in, const int* in_sizes, int n_in,
                              void* d_out, int out_size)
{
    const float* h  = (const float*)d_in[0];   // (B,S,D)
    const float* rw = (const float*)d_in[1];   // (D,E)
    const float* w1 = (const float*)d_in[2];   // (E,D,F)
    const float* b1 = (const float*)d_in[3];   // (E,F)
    const float* w2 = (const float*)d_in[4];   // (E,F,D)
    const float* b2 = (const float*)d_in[5];   // (E,D)
    float* out = (float*)d_out;                // (B,S,D)

    cudaFuncSetAttribute(gemm_mma_kernel<DD, FF, false>,
                         cudaFuncAttributeMaxDynamicSharedMemorySize, SMEM_GEMM);
    cudaFuncSetAttribute(gemm_mma_kernel<FF, DD, true>,
                         cudaFuncAttributeMaxDynamicSharedMemorySize, SMEM_GEMM);
    cudaFuncSetAttribute(router_kernel,
                         cudaFuncAttributeMaxDynamicSharedMemorySize, SMEM_RT);

    __half *xh, *hh;
    cudaGetSymbolAddress((void**)&xh, g_xh);
    cudaGetSymbolAddress((void**)&hh, g_hh);

    router_kernel<<<NTOK / RT_WARPS, 512, SMEM_RT>>>(h, rw);
    plan_kernel<<<1, 32>>>();
    scatter_gather_kernel<<<NTOK, 256>>>(h);

    gemm_mma_kernel<DD, FF, false><<<dim3(GRID_X, FF / BN), NTHREADS_G, SMEM_GEMM>>>(
        xh, w1, b1, nullptr);
    gemm_mma_kernel<FF, DD, true><<<dim3(GRID_X, DD / BN), NTHREADS_G, SMEM_GEMM>>>(
        hh, w2, b2, out);
}